// round 6
// baseline (speedup 1.0000x reference)
#include <cuda_runtime.h>
#include <cuda_fp16.h>
#include <math.h>

#define NB 256
#define NJ 10
#define NI 1152
#define NP 16
#define NQ 8
#define NICH 18         // i-chunks for k_hat (64 i each)
#define NCH 9           // i-chunks for route
#define CH 128          // i per route chunk
#define JP (NJ * NP)    // 160
#define CBS 136         // cbuf stride (bank-pad)
#define JST 1032        // uint words per j-block in smem hat (1024 + 8 pad)
#define RT 320          // route block threads

// Scratch (device globals — no allocation anywhere). Zero-init at load;
// g_cnt is self-resetting (last block clears it) so graph replays are clean.
__device__ __half g_hat[(size_t)NB * NJ * NI * NP];     // [b][j][i][p], 94.4 MB
__device__ float  g_s0part[NICH * NB * JP];             // [ic][b][j*16+p]
__device__ float  g_spartB[NB * NCH * JP];              // pass-B partials
__device__ float  g_spartC[NB * NCH * JP];              // pass-C partials
__device__ unsigned int g_cnt[NB];                      // pass-C completion counters

// ---------------------------------------------------------------------------
// K1: hat[b,j,i,p] = sum_q W[j,i,p,q]*in[b,i,q] in half2 (HFMA2), fp16 store.
// Double-buffered input staging (1 sync per 8-batch group). s0 partials via
// half2 butterfly -> double-buffered SMEM slots -> deterministic global slots.
// grid (ic=18, j=10, bc=4), block 256. Thread owns (i, p-quad).
// ---------------------------------------------------------------------------
__global__ __launch_bounds__(256) void k_hat(const float* __restrict__ in,
                                             const float* __restrict__ W) {
    const int ic = blockIdx.x;
    const int j  = blockIdx.y;
    const int bc = blockIdx.z;
    const int t  = threadIdx.x;
    const int p4 = t & 3;
    const int il = t >> 2;
    const int i  = ic * 64 + il;
    const int lane = t & 31;
    const int wrp  = t >> 5;

    __half2 w01[8], w23[8];
    {
        float w[4][8];
        const float4* Wv = (const float4*)(W + ((size_t)(j * NI + i) * NP + p4 * 4) * NQ);
        #pragma unroll
        for (int pp = 0; pp < 4; pp++) {
            float4 a = Wv[pp * 2], c = Wv[pp * 2 + 1];
            w[pp][0] = a.x; w[pp][1] = a.y; w[pp][2] = a.z; w[pp][3] = a.w;
            w[pp][4] = c.x; w[pp][5] = c.y; w[pp][6] = c.z; w[pp][7] = c.w;
        }
        #pragma unroll
        for (int q = 0; q < 8; q++) {
            w01[q] = __floats2half2_rn(w[0][q], w[1][q]);
            w23[q] = __floats2half2_rn(w[2][q], w[3][q]);
        }
    }

    __shared__ __half2 in_s[2][8 * 64 * NQ];   // 2 x 16 KB
    __shared__ float   s0w[2][8 * 128];        // 2 x 4 KB

    // staging helper (lambda-free, inline twice via macro-style code)
    #define LOAD_GROUP(gg, buf)                                                      \
        {                                                                            \
            const int b0L = bc * 64 + (gg) * 8;                                      \
            _Pragma("unroll")                                                        \
            for (int k = 0; k < 4; k++) {                                            \
                int m   = t + 256 * k;                                               \
                int bo  = m >> 7;                                                    \
                int pos = m & 127;                                                   \
                float4 v = ((const float4*)(in +                                     \
                    ((size_t)(b0L + bo) * NI + ic * 64) * NQ))[pos];                 \
                __half2* dst = in_s[buf] + (size_t)bo * 512 + pos * 4;               \
                dst[0] = __floats2half2_rn(v.x, v.x);                                \
                dst[1] = __floats2half2_rn(v.y, v.y);                                \
                dst[2] = __floats2half2_rn(v.z, v.z);                                \
                dst[3] = __floats2half2_rn(v.w, v.w);                                \
            }                                                                        \
        }

    LOAD_GROUP(0, 0);
    __syncthreads();

    for (int g = 0; g < 8; g++) {
        const int cur = g & 1;
        const int b0 = bc * 64 + g * 8;
        if (g < 7) LOAD_GROUP(g + 1, cur ^ 1);

        #pragma unroll
        for (int bb = 0; bb < 8; bb++) {
            const int b = b0 + bb;
            const __half2* xs = in_s[cur] + (bb * 64 + il) * NQ;
            __half2 x0 = xs[0], x1 = xs[1], x2 = xs[2], x3 = xs[3];
            __half2 x4 = xs[4], x5 = xs[5], x6 = xs[6], x7 = xs[7];

            __half2 c0 = __hmul2(x0, w01[0]);
            c0 = __hfma2(x1, w01[1], c0);
            c0 = __hfma2(x2, w01[2], c0);
            c0 = __hfma2(x3, w01[3], c0);
            __half2 c1 = __hmul2(x4, w01[4]);
            c1 = __hfma2(x5, w01[5], c1);
            c1 = __hfma2(x6, w01[6], c1);
            c1 = __hfma2(x7, w01[7], c1);
            __half2 r01 = __hadd2(c0, c1);

            __half2 d0 = __hmul2(x0, w23[0]);
            d0 = __hfma2(x1, w23[1], d0);
            d0 = __hfma2(x2, w23[2], d0);
            d0 = __hfma2(x3, w23[3], d0);
            __half2 d1 = __hmul2(x4, w23[4]);
            d1 = __hfma2(x5, w23[5], d1);
            d1 = __hfma2(x6, w23[6], d1);
            d1 = __hfma2(x7, w23[7], d1);
            __half2 r23 = __hadd2(d0, d1);

            union { __half2 h2[2]; uint2 u; } pk;
            pk.h2[0] = r01; pk.h2[1] = r23;
            *(uint2*)(g_hat + ((size_t)(b * NJ + j) * NI + i) * NP + p4 * 4) = pk.u;

            union { __half2 h; unsigned int u; } s01, s23;
            s01.h = r01; s23.h = r23;
            #pragma unroll
            for (int d2 = 4; d2 <= 16; d2 <<= 1) {
                union { __half2 h; unsigned int u; } o1, o2;
                o1.u = __shfl_xor_sync(0xffffffffu, s01.u, d2);
                o2.u = __shfl_xor_sync(0xffffffffu, s23.u, d2);
                s01.h = __hadd2(s01.h, o1.h);
                s23.h = __hadd2(s23.h, o2.h);
            }
            if (lane < 4) {
                float2 f01 = __half22float2(s01.h);
                float2 f23 = __half22float2(s23.h);
                float4 v; v.x = f01.x; v.y = f01.y; v.z = f23.x; v.w = f23.y;
                *(float4*)(&s0w[cur][wrp * 128 + bb * 16 + lane * 4]) = v;
            }
        }
        __syncthreads();   // single sync: in_s[cur^1] filled, s0w[cur] complete
        if (t < 128) {     // deterministic flush (reads s0w[cur]; next iter uses s0w[cur^1])
            int bb2 = t >> 4, p = t & 15;
            float a = 0.f;
            #pragma unroll
            for (int w8 = 0; w8 < 8; w8++) a += s0w[cur][w8 * 128 + t];
            g_s0part[(ic * NB + b0 + bb2) * JP + j * NP + p] = a;
        }
    }
    #undef LOAD_GROUP
}

// ---------------------------------------------------------------------------
// K2/K3: one routing pass, 320 threads. Head: routing vector. Phase 1 (4
// iters): load+stage chunk, half2 dot -> logits. Phase 2: softmax. Phase 3:
// il-split (2x160) weighted column sum. Pass C: last block per b does the
// final squash -> d_out (threadfence + counter, deterministic sum order).
// grid (ic=9, b=256), block 320.
// ---------------------------------------------------------------------------
__global__ __launch_bounds__(RT) void k_route(const float* __restrict__ spart_in,
                                              float* __restrict__ spart_out,
                                              int pass,
                                              float* __restrict__ out) {
    const int ic = blockIdx.x;
    const int b  = blockIdx.y;
    const int t  = threadIdx.x;

    __shared__ __align__(16) unsigned int smh[NJ * JST];  // hat chunk, 41.3 KB
    __shared__ float   cbuf[NJ * CBS];
    __shared__ float   ov[JP];
    __shared__ __half2 ovh[JP / 2];
    __shared__ float   p3buf[RT];
    __shared__ int     isLast;

    if (t < JP) {
        float s = 0.f;
        #pragma unroll
        for (int c2 = 0; c2 < NICH; c2++) s += g_s0part[(c2 * NB + b) * JP + t];
        s *= 0.1f;
        float sq = s * s;
        sq += __shfl_xor_sync(0xffffffffu, sq, 1);
        sq += __shfl_xor_sync(0xffffffffu, sq, 2);
        sq += __shfl_xor_sync(0xffffffffu, sq, 4);
        sq += __shfl_xor_sync(0xffffffffu, sq, 8);
        float sc = sq / ((1.f + sq) * sqrtf(sq + 1e-7f));
        float v = s * sc;                      // out0
        if (pass) {
            float s1 = 0.f;
            #pragma unroll
            for (int c2 = 0; c2 < NCH; c2++)
                s1 += spart_in[(b * NCH + c2) * JP + t];
            float q = s1 * s1;
            q += __shfl_xor_sync(0xffffffffu, q, 1);
            q += __shfl_xor_sync(0xffffffffu, q, 2);
            q += __shfl_xor_sync(0xffffffffu, q, 4);
            q += __shfl_xor_sync(0xffffffffu, q, 8);
            float sc1 = q / ((1.f + q) * sqrtf(q + 1e-7f));
            v += s1 * sc1;                     // out0 + out1
        }
        ov[t] = v;
    }
    __syncthreads();
    if (t < JP / 2) ovh[t] = __floats2half2_rn(ov[2 * t], ov[2 * t + 1]);
    __syncthreads();

    const __half* hb = g_hat + (size_t)b * NJ * NI * NP;
    const int i0 = ic * CH;

    // Phase 1: load + stage + logits (half2 dot), 1280 rows / 320 threads
    #pragma unroll
    for (int k = 0; k < 4; k++) {
        int idx = t + RT * k;           // 0..1279
        int j = idx >> 7, il = idx & 127;
        const __half* h = hb + (size_t)(j * NI + i0 + il) * NP;
        union { uint4 u; __half2 h2[4]; } a, c;
        a.u = ((const uint4*)h)[0];
        c.u = ((const uint4*)h)[1];
        const __half2* av = ovh + j * 8;
        __half2 acc0 = __hmul2(a.h2[0], av[0]);
        acc0 = __hfma2(a.h2[1], av[1], acc0);
        acc0 = __hfma2(a.h2[2], av[2], acc0);
        acc0 = __hfma2(a.h2[3], av[3], acc0);
        __half2 acc1 = __hmul2(c.h2[0], av[4]);
        acc1 = __hfma2(c.h2[1], av[5], acc1);
        acc1 = __hfma2(c.h2[2], av[6], acc1);
        acc1 = __hfma2(c.h2[3], av[7], acc1);
        float2 f = __half22float2(__hadd2(acc0, acc1));
        cbuf[j * CBS + il] = f.x + f.y;
        uint4* dst = (uint4*)(smh + j * JST + il * 8);
        dst[0] = a.u;
        dst[1] = c.u;
    }
    __syncthreads();

    // Phase 2: softmax over j per i
    if (t < CH) {
        float v[NJ];
        float mx = -1e30f;
        #pragma unroll
        for (int j = 0; j < NJ; j++) { v[j] = cbuf[j * CBS + t]; mx = fmaxf(mx, v[j]); }
        float sum = 0.f;
        #pragma unroll
        for (int j = 0; j < NJ; j++) { v[j] = __expf(v[j] - mx); sum += v[j]; }
        float inv = 1.f / sum;
        #pragma unroll
        for (int j = 0; j < NJ; j++) cbuf[j * CBS + t] = v[j] * inv;
    }
    __syncthreads();

    // Phase 3: il-split weighted column sum (group 0: il 0..63, group 1: 64..127)
    {
        const int jp = (t < JP) ? t : t - JP;
        const int j = jp >> 4, p = jp & 15;
        const int il0 = (t < JP) ? 0 : 64;
        const __half* hrow = (const __half*)(smh + j * JST) + p;
        const float* cc = cbuf + j * CBS;
        float a0 = 0.f, a1 = 0.f, a2 = 0.f, a3 = 0.f;
        #pragma unroll
        for (int il = il0; il < il0 + 64; il += 4) {
            a0 = fmaf(__half2float(hrow[(il + 0) * 16]), cc[il + 0], a0);
            a1 = fmaf(__half2float(hrow[(il + 1) * 16]), cc[il + 1], a1);
            a2 = fmaf(__half2float(hrow[(il + 2) * 16]), cc[il + 2], a2);
            a3 = fmaf(__half2float(hrow[(il + 3) * 16]), cc[il + 3], a3);
        }
        p3buf[t] = (a0 + a1) + (a2 + a3);
    }
    __syncthreads();
    if (t < JP) spart_out[(b * NCH + ic) * JP + t] = p3buf[t] + p3buf[t + JP];

    // Pass C: last block for this b performs the final reduction + squash.
    if (pass) {
        __threadfence();
        __syncthreads();
        if (t == 0) {
            unsigned int old = atomicAdd(&g_cnt[b], 1u);
            isLast = (old == NCH - 1) ? 1 : 0;
            if (isLast) __threadfence();     // acquire side
        }
        __syncthreads();
        if (isLast) {
            if (t == 0) g_cnt[b] = 0;        // reset for next graph replay
            if (t < JP) {
                float acc = 0.f;
                #pragma unroll
                for (int c2 = 0; c2 < NCH; c2++)
                    acc += spart_out[(b * NCH + c2) * JP + t];
                float sq = acc * acc;
                sq += __shfl_xor_sync(0xffffffffu, sq, 1);
                sq += __shfl_xor_sync(0xffffffffu, sq, 2);
                sq += __shfl_xor_sync(0xffffffffu, sq, 4);
                sq += __shfl_xor_sync(0xffffffffu, sq, 8);
                float sc = sq / ((1.f + sq) * sqrtf(sq + 1e-7f));
                out[b * JP + t] = acc * sc;
            }
        }
    }
}

extern "C" void kernel_launch(void* const* d_in, const int* in_sizes, int n_in,
                              void* d_out, int out_size) {
    const float* in = (const float*)d_in[0];   // [256,1152,8]
    const float* W  = (const float*)d_in[1];   // [10,1152,16,8]
    float* out = (float*)d_out;                // [256,10,16]

    void* pB = nullptr; cudaGetSymbolAddress(&pB, g_spartB);
    void* pC = nullptr; cudaGetSymbolAddress(&pC, g_spartC);

    k_hat<<<dim3(NICH, NJ, 4), 256>>>(in, W);
    k_route<<<dim3(NCH, NB), RT>>>((const float*)pB, (float*)pB, 0, out);  // pass B
    k_route<<<dim3(NCH, NB), RT>>>((const float*)pB, (float*)pC, 1, out);  // pass C + final
}

// round 7
// speedup vs baseline: 1.0647x; 1.0647x over previous
#include <cuda_runtime.h>
#include <cuda_fp16.h>
#include <math.h>

#define NB 256
#define NJ 10
#define NI 1152
#define NP 16
#define NQ 8
#define NICH 18         // i-chunks for k_hat (64 i each)
#define NCH 9           // i-chunks for route
#define CH 128          // i per route chunk
#define JP (NJ * NP)    // 160
#define CBS 136         // cbuf stride (bank-pad)
#define JST 1032        // uint words per j-block in smem hat (1024+8 pad = 8-bank rotate)

// Scratch (device globals — no allocation anywhere).
__device__ __half g_hat[(size_t)NB * NJ * NI * NP];     // [b][j][i][p], 94.4 MB
__device__ float  g_s0part[NICH * NB * JP];             // [ic][b][j*16+p]
__device__ float  g_spartB[NB * NCH * JP];              // pass-B partials
__device__ float  g_spartC[NB * NCH * JP];              // pass-C partials

// ---------------------------------------------------------------------------
// K1: hat[b,j,i,p] = sum_q W[j,i,p,q]*in[b,i,q] in half2 (HFMA2), fp16 store.
// Vectorized SMEM: staging = STS.128 of packed dup-half2; operand fetch =
// 2x LDS.128 per batch. s0 via half2 butterfly -> SMEM slots -> global slots.
// grid (ic=18, j=10, bc=4), block 256. Thread owns (i, p-quad).
// ---------------------------------------------------------------------------
__global__ __launch_bounds__(256) void k_hat(const float* __restrict__ in,
                                             const float* __restrict__ W) {
    const int ic = blockIdx.x;
    const int j  = blockIdx.y;
    const int bc = blockIdx.z;
    const int t  = threadIdx.x;
    const int p4 = t & 3;
    const int il = t >> 2;
    const int i  = ic * 64 + il;
    const int lane = t & 31;
    const int wrp  = t >> 5;

    __half2 w01[8], w23[8];
    {
        float w[4][8];
        const float4* Wv = (const float4*)(W + ((size_t)(j * NI + i) * NP + p4 * 4) * NQ);
        #pragma unroll
        for (int pp = 0; pp < 4; pp++) {
            float4 a = Wv[pp * 2], c = Wv[pp * 2 + 1];
            w[pp][0] = a.x; w[pp][1] = a.y; w[pp][2] = a.z; w[pp][3] = a.w;
            w[pp][4] = c.x; w[pp][5] = c.y; w[pp][6] = c.z; w[pp][7] = c.w;
        }
        #pragma unroll
        for (int q = 0; q < 8; q++) {
            w01[q] = __floats2half2_rn(w[0][q], w[1][q]);
            w23[q] = __floats2half2_rn(w[2][q], w[3][q]);
        }
    }

    __shared__ __align__(16) uint4 in_s[8 * 64 * 2];   // dup half2 packed, 16 KB
    __shared__ float s0w[8 * 128];                     // [warp][bb*16+p], 4 KB

    for (int g = 0; g < 8; g++) {
        const int b0 = bc * 64 + g * 8;
        __syncthreads();                  // in_s + s0w reuse safe
        #pragma unroll
        for (int k = 0; k < 4; k++) {
            int m   = t + 256 * k;        // float4 index 0..1023
            int bo  = m >> 7;             // 128 float4 per b
            int pos = m & 127;
            float4 v = ((const float4*)(in + ((size_t)(b0 + bo) * NI + ic * 64) * NQ))[pos];
            union { __half2 h[4]; uint4 u; } pk;
            pk.h[0] = __floats2half2_rn(v.x, v.x);
            pk.h[1] = __floats2half2_rn(v.y, v.y);
            pk.h[2] = __floats2half2_rn(v.z, v.z);
            pk.h[3] = __floats2half2_rn(v.w, v.w);
            in_s[bo * 128 + pos] = pk.u;   // STS.128
        }
        __syncthreads();
        #pragma unroll
        for (int bb = 0; bb < 8; bb++) {
            const int b = b0 + bb;
            union { uint4 u; __half2 h[4]; } xa, xb;
            xa.u = in_s[(bb * 64 + il) * 2 + 0];   // LDS.128
            xb.u = in_s[(bb * 64 + il) * 2 + 1];   // LDS.128

            __half2 c0 = __hmul2(xa.h[0], w01[0]);
            c0 = __hfma2(xa.h[1], w01[1], c0);
            c0 = __hfma2(xa.h[2], w01[2], c0);
            c0 = __hfma2(xa.h[3], w01[3], c0);
            __half2 c1 = __hmul2(xb.h[0], w01[4]);
            c1 = __hfma2(xb.h[1], w01[5], c1);
            c1 = __hfma2(xb.h[2], w01[6], c1);
            c1 = __hfma2(xb.h[3], w01[7], c1);
            __half2 r01 = __hadd2(c0, c1);

            __half2 d0 = __hmul2(xa.h[0], w23[0]);
            d0 = __hfma2(xa.h[1], w23[1], d0);
            d0 = __hfma2(xa.h[2], w23[2], d0);
            d0 = __hfma2(xa.h[3], w23[3], d0);
            __half2 d1 = __hmul2(xb.h[0], w23[4]);
            d1 = __hfma2(xb.h[1], w23[5], d1);
            d1 = __hfma2(xb.h[2], w23[6], d1);
            d1 = __hfma2(xb.h[3], w23[7], d1);
            __half2 r23 = __hadd2(d0, d1);

            union { __half2 h2[2]; uint2 u; } pk;
            pk.h2[0] = r01; pk.h2[1] = r23;
            *(uint2*)(g_hat + ((size_t)(b * NJ + j) * NI + i) * NP + p4 * 4) = pk.u;

            union { __half2 h; unsigned int u; } s01, s23;
            s01.h = r01; s23.h = r23;
            #pragma unroll
            for (int d2 = 4; d2 <= 16; d2 <<= 1) {
                union { __half2 h; unsigned int u; } o1, o2;
                o1.u = __shfl_xor_sync(0xffffffffu, s01.u, d2);
                o2.u = __shfl_xor_sync(0xffffffffu, s23.u, d2);
                s01.h = __hadd2(s01.h, o1.h);
                s23.h = __hadd2(s23.h, o2.h);
            }
            if (lane < 4) {                  // lane == p4 here
                float2 f01 = __half22float2(s01.h);
                float2 f23 = __half22float2(s23.h);
                float4 v; v.x = f01.x; v.y = f01.y; v.z = f23.x; v.w = f23.y;
                *(float4*)(&s0w[wrp * 128 + bb * 16 + lane * 4]) = v;
            }
        }
        __syncthreads();                     // s0w complete
        if (t < 128) {                       // deterministic flush, no atomics
            int bb2 = t >> 4, p = t & 15;
            float a = 0.f;
            #pragma unroll
            for (int w8 = 0; w8 < 8; w8++) a += s0w[w8 * 128 + t];
            g_s0part[(ic * NB + b0 + bb2) * JP + j * NP + p] = a;
        }
    }
}

// ---------------------------------------------------------------------------
// K2/K3: one routing pass. Head: routing vector (out0 [+ squash(s_prev)]).
// Phase 1: load hat chunk (half2 dot via LDS.128 operands), stage in SMEM.
// Phase 2: softmax. Phase 3: p-pair threads, half2 loads, il-split 2x80.
// grid (ic=9, b=256), block 256.
// ---------------------------------------------------------------------------
__global__ __launch_bounds__(256) void k_route(const float* __restrict__ spart_in,
                                               float* __restrict__ spart_out,
                                               int pass) {
    const int ic = blockIdx.x;
    const int b  = blockIdx.y;
    const int t  = threadIdx.x;

    __shared__ __align__(16) unsigned int smh[NJ * JST];  // hat chunk, 41.3 KB
    __shared__ float   cbuf[NJ * CBS];
    __shared__ float   ov[JP];
    __shared__ __align__(16) __half2 ovh[JP / 2];
    __shared__ float2  p3buf[160];

    if (t < JP) {
        float s = 0.f;
        #pragma unroll
        for (int c2 = 0; c2 < NICH; c2++) s += g_s0part[(c2 * NB + b) * JP + t];
        s *= 0.1f;                             // c0 = 1/J exactly
        float sq = s * s;
        sq += __shfl_xor_sync(0xffffffffu, sq, 1);
        sq += __shfl_xor_sync(0xffffffffu, sq, 2);
        sq += __shfl_xor_sync(0xffffffffu, sq, 4);
        sq += __shfl_xor_sync(0xffffffffu, sq, 8);
        float sc = sq / ((1.f + sq) * sqrtf(sq + 1e-7f));
        float v = s * sc;                      // out0
        if (pass) {
            float s1 = 0.f;
            #pragma unroll
            for (int c2 = 0; c2 < NCH; c2++)
                s1 += spart_in[(b * NCH + c2) * JP + t];
            float q = s1 * s1;
            q += __shfl_xor_sync(0xffffffffu, q, 1);
            q += __shfl_xor_sync(0xffffffffu, q, 2);
            q += __shfl_xor_sync(0xffffffffu, q, 4);
            q += __shfl_xor_sync(0xffffffffu, q, 8);
            float sc1 = q / ((1.f + q) * sqrtf(q + 1e-7f));
            v += s1 * sc1;                     // out0 + out1
        }
        ov[t] = v;
    }
    __syncthreads();
    if (t < JP / 2) ovh[t] = __floats2half2_rn(ov[2 * t], ov[2 * t + 1]);
    __syncthreads();

    const __half* hb = g_hat + (size_t)b * NJ * NI * NP;
    const int i0 = ic * CH;

    // Phase 1: load + stage + logits (half2 dot, LDS.128 routing vector)
    #pragma unroll
    for (int k = 0; k < 5; k++) {
        int idx = t + 256 * k;          // 0..1279
        int j = idx >> 7, il = idx & 127;
        const __half* h = hb + (size_t)(j * NI + i0 + il) * NP;
        union { uint4 u; __half2 h2[4]; } a, c, va, vb;
        a.u = ((const uint4*)h)[0];
        c.u = ((const uint4*)h)[1];
        const uint4* avv = (const uint4*)(ovh + j * 8);
        va.u = avv[0];                  // LDS.128
        vb.u = avv[1];                  // LDS.128
        __half2 acc0 = __hmul2(a.h2[0], va.h2[0]);
        acc0 = __hfma2(a.h2[1], va.h2[1], acc0);
        acc0 = __hfma2(a.h2[2], va.h2[2], acc0);
        acc0 = __hfma2(a.h2[3], va.h2[3], acc0);
        __half2 acc1 = __hmul2(c.h2[0], vb.h2[0]);
        acc1 = __hfma2(c.h2[1], vb.h2[1], acc1);
        acc1 = __hfma2(c.h2[2], vb.h2[2], acc1);
        acc1 = __hfma2(c.h2[3], vb.h2[3], acc1);
        float2 f = __half22float2(__hadd2(acc0, acc1));
        cbuf[j * CBS + il] = f.x + f.y;
        uint4* dst = (uint4*)(smh + j * JST + il * 8);
        dst[0] = a.u;
        dst[1] = c.u;
    }
    __syncthreads();

    // Phase 2: softmax over j per i
    if (t < CH) {
        float v[NJ];
        float mx = -1e30f;
        #pragma unroll
        for (int j = 0; j < NJ; j++) { v[j] = cbuf[j * CBS + t]; mx = fmaxf(mx, v[j]); }
        float sum = 0.f;
        #pragma unroll
        for (int j = 0; j < NJ; j++) { v[j] = __expf(v[j] - mx); sum += v[j]; }
        float inv = 1.f / sum;
        #pragma unroll
        for (int j = 0; j < NJ; j++) cbuf[j * CBS + t] = v[j] * inv;
    }
    __syncthreads();

    // Phase 3: p-pair threads (t<160): grp = il-half, pp = (j, p-pair).
    // hrow addresses: word (j*1032 + il*8 + pj) -> banks (j*8+pj+il*8)%32:
    // 32 distinct banks per warp -> conflict-free.
    if (t < 160) {
        const int grp = t / 80;          // il half: 0 or 1
        const int pp  = t % 80;
        const int j = pp >> 3, pj = pp & 7;
        const __half2* hrow = (const __half2*)(smh + j * JST) + pj;  // 8 half2 per il
        const float* cc = cbuf + j * CBS;
        const int il0 = grp * 64;
        float ax = 0.f, ay = 0.f, bx = 0.f, by = 0.f;
        #pragma unroll
        for (int il = il0; il < il0 + 64; il += 2) {
            float2 f0 = __half22float2(hrow[(il + 0) * 8]);
            float2 f1 = __half22float2(hrow[(il + 1) * 8]);
            float c0 = cc[il], c1 = cc[il + 1];
            ax = fmaf(f0.x, c0, ax);
            ay = fmaf(f0.y, c0, ay);
            bx = fmaf(f1.x, c1, bx);
            by = fmaf(f1.y, c1, by);
        }
        float2 r; r.x = ax + bx; r.y = ay + by;
        p3buf[t] = r;
    }
    __syncthreads();
    if (t < 80) {
        float2 r0 = p3buf[t], r1 = p3buf[t + 80];
        float2 r; r.x = r0.x + r1.x; r.y = r0.y + r1.y;
        *(float2*)(spart_out + (b * NCH + ic) * JP + t * 2) = r;
    }
}

// ---------------------------------------------------------------------------
// K4: final = squash(sum of pass-C partials) -> d_out.
// ---------------------------------------------------------------------------
__global__ __launch_bounds__(160) void k_final(float* __restrict__ out) {
    const int b = blockIdx.x, t = threadIdx.x;
    float acc = 0.f;
    #pragma unroll
    for (int c2 = 0; c2 < NCH; c2++) acc += g_spartC[(b * NCH + c2) * JP + t];
    float sq = acc * acc;
    sq += __shfl_xor_sync(0xffffffffu, sq, 1);
    sq += __shfl_xor_sync(0xffffffffu, sq, 2);
    sq += __shfl_xor_sync(0xffffffffu, sq, 4);
    sq += __shfl_xor_sync(0xffffffffu, sq, 8);
    float sc = sq / ((1.f + sq) * sqrtf(sq + 1e-7f));
    out[b * JP + t] = acc * sc;
}

extern "C" void kernel_launch(void* const* d_in, const int* in_sizes, int n_in,
                              void* d_out, int out_size) {
    const float* in = (const float*)d_in[0];   // [256,1152,8]
    const float* W  = (const float*)d_in[1];   // [10,1152,16,8]
    float* out = (float*)d_out;                // [256,10,16]

    void* pB = nullptr; cudaGetSymbolAddress(&pB, g_spartB);
    void* pC = nullptr; cudaGetSymbolAddress(&pC, g_spartC);

    k_hat<<<dim3(NICH, NJ, 4), 256>>>(in, W);
    k_route<<<dim3(NCH, NB), 256>>>((const float*)pB, (float*)pB, 0);  // pass B
    k_route<<<dim3(NCH, NB), 256>>>((const float*)pB, (float*)pC, 1);  // pass C
    k_final<<<NB, 160>>>(out);
}